// round 1
// baseline (speedup 1.0000x reference)
#include <cuda_runtime.h>
#include <math.h>

#define BB 4096
#define TT 200
#define DD 64
#define H1 80
#define H2 40
#define NEG_BIG_F (-4294967295.0f)

// One block per batch element b. 256 threads.
// Phase 1: build per-b folded weight Wk[j][i] = W1b - W1c + q_i*W1d  (shared),
//          per-b bias c[j] = b1[j] + q @ (W1a + W1c), copy W2/b2/Wf to shared.
// Phase 2: thread t (t<200) computes the MLP score with k_t in registers.
// Phase 3: block softmax over 200 scores.
// Phase 4: out[b][:] = attn @ V_b  (64 dims x 4 partial sums).
__global__ __launch_bounds__(256, 2)
void din_attn_kernel(const float* __restrict__ q, const float* __restrict__ k,
                     const float* __restrict__ v, const int* __restrict__ mask,
                     const float* __restrict__ W1, const float* __restrict__ b1,
                     const float* __restrict__ W2, const float* __restrict__ b2,
                     const float* __restrict__ Wf, const float* __restrict__ bf,
                     float* __restrict__ out)
{
    __shared__ __align__(16) float q_sh[DD];
    __shared__ __align__(16) float Wk_sh[H1 * DD];    // [j][i], row = 64 floats (256B)
    __shared__ __align__(16) float W2_sh[H1 * H2];    // [j][g], row = 40 floats (160B)
    __shared__ __align__(16) float c_sh[H1];
    __shared__ __align__(16) float b2_sh[H2];
    __shared__ __align__(16) float Wf_sh[H2];
    __shared__ float sc_sh[TT];
    __shared__ float red_sh[8];
    __shared__ float part_sh[256];
    __shared__ float mx_sh, inv_sh;

    const int tid = threadIdx.x;
    const int b   = blockIdx.x;

    if (tid < DD) q_sh[tid] = q[b * DD + tid];
    __syncthreads();

    // ---- Phase 1: fold weights ----
    for (int idx = tid; idx < DD * H1; idx += 256) {
        int i = idx / H1;
        int j = idx % H1;
        float w = W1[(64 + i) * H1 + j]            // W1b (k)
                - W1[(128 + i) * H1 + j]           // -W1c (q-k)
                + q_sh[i] * W1[(192 + i) * H1 + j]; // q_i * W1d (q*k)
        Wk_sh[j * DD + i] = w;
    }
    for (int idx = tid; idx < H1 * H2; idx += 256) W2_sh[idx] = W2[idx];
    if (tid < H2) { b2_sh[tid] = b2[tid]; Wf_sh[tid] = Wf[tid]; }
    if (tid < H1) {
        float acc = b1[tid];
        #pragma unroll 8
        for (int i = 0; i < DD; i++)
            acc += q_sh[i] * (W1[i * H1 + tid] + W1[(128 + i) * H1 + tid]);
        c_sh[tid] = acc;
    }
    __syncthreads();

    // ---- Phase 2: per-token MLP score ----
    if (tid < TT) {
        const float4* kp = (const float4*)(k + ((size_t)b * TT + tid) * DD);
        float4 kk[16];
        #pragma unroll
        for (int ii = 0; ii < 16; ii++) kk[ii] = kp[ii];

        float4 h2a[10];
        #pragma unroll
        for (int g = 0; g < 10; g++) h2a[g] = ((const float4*)b2_sh)[g];

        for (int j = 0; j < H1; j++) {
            float acc = c_sh[j];
            const float4* wr = (const float4*)(Wk_sh + j * DD);
            #pragma unroll
            for (int ii = 0; ii < 16; ii++) {
                float4 w = wr[ii];
                acc = fmaf(kk[ii].x, w.x, acc);
                acc = fmaf(kk[ii].y, w.y, acc);
                acc = fmaf(kk[ii].z, w.z, acc);
                acc = fmaf(kk[ii].w, w.w, acc);
            }
            float h = fmaxf(acc, 0.0f);
            const float4* w2r = (const float4*)(W2_sh + j * H2);
            #pragma unroll
            for (int g = 0; g < 10; g++) {
                float4 w = w2r[g];
                h2a[g].x = fmaf(h, w.x, h2a[g].x);
                h2a[g].y = fmaf(h, w.y, h2a[g].y);
                h2a[g].z = fmaf(h, w.z, h2a[g].z);
                h2a[g].w = fmaf(h, w.w, h2a[g].w);
            }
        }
        float s = bf[0];
        const float4* wfr = (const float4*)Wf_sh;
        #pragma unroll
        for (int g = 0; g < 10; g++) {
            float4 w = wfr[g];
            s = fmaf(fmaxf(h2a[g].x, 0.0f), w.x, s);
            s = fmaf(fmaxf(h2a[g].y, 0.0f), w.y, s);
            s = fmaf(fmaxf(h2a[g].z, 0.0f), w.z, s);
            s = fmaf(fmaxf(h2a[g].w, 0.0f), w.w, s);
        }
        if (mask[(size_t)b * TT + tid] == 0) s = NEG_BIG_F;
        sc_sh[tid] = s;
    }
    __syncthreads();

    // ---- Phase 3: softmax over T ----
    float mval = (tid < TT) ? sc_sh[tid] : -3.0e38f;
    #pragma unroll
    for (int o = 16; o; o >>= 1)
        mval = fmaxf(mval, __shfl_xor_sync(0xffffffffu, mval, o));
    if ((tid & 31) == 0) red_sh[tid >> 5] = mval;
    __syncthreads();
    if (tid == 0) {
        float m = red_sh[0];
        #pragma unroll
        for (int w = 1; w < 8; w++) m = fmaxf(m, red_sh[w]);
        mx_sh = m;
    }
    __syncthreads();
    const float mx = mx_sh;
    float e = (tid < TT) ? __expf(sc_sh[tid] - mx) : 0.0f;
    if (tid < TT) sc_sh[tid] = e;   // own slot only; no cross-thread hazard
    float sval = e;
    #pragma unroll
    for (int o = 16; o; o >>= 1)
        sval += __shfl_xor_sync(0xffffffffu, sval, o);
    if ((tid & 31) == 0) red_sh[tid >> 5] = sval;
    __syncthreads();
    if (tid == 0) {
        float sm = 0.0f;
        #pragma unroll
        for (int w = 0; w < 8; w++) sm += red_sh[w];
        inv_sh = 1.0f / sm;
    }
    __syncthreads();

    // ---- Phase 4: out = attn @ V ----
    const float inv = inv_sh;
    const int dd = tid & 63;
    const int p  = tid >> 6;          // 4 partial-sum groups of 50 tokens
    const float* vb = v + (size_t)b * TT * DD;
    float acc = 0.0f;
    const int t0 = p * 50;
    #pragma unroll 5
    for (int t = t0; t < t0 + 50; t++)
        acc = fmaf(sc_sh[t], vb[(size_t)t * DD + dd], acc);
    part_sh[tid] = acc;
    __syncthreads();
    if (tid < DD) {
        float r = part_sh[tid] + part_sh[tid + 64] + part_sh[tid + 128] + part_sh[tid + 192];
        out[(size_t)b * DD + tid] = r * inv;
    }
}

extern "C" void kernel_launch(void* const* d_in, const int* in_sizes, int n_in,
                              void* d_out, int out_size)
{
    const float* q    = (const float*)d_in[0];
    const float* k    = (const float*)d_in[1];
    const float* v    = (const float*)d_in[2];
    const int*   mask = (const int*)  d_in[3];
    const float* W1   = (const float*)d_in[4];
    const float* b1   = (const float*)d_in[5];
    const float* W2   = (const float*)d_in[6];
    const float* b2   = (const float*)d_in[7];
    const float* Wf   = (const float*)d_in[8];
    const float* bf   = (const float*)d_in[9];
    float* out = (float*)d_out;

    din_attn_kernel<<<BB, 256>>>(q, k, v, mask, W1, b1, W2, b2, Wf, bf, out);
}

// round 2
// speedup vs baseline: 1.1910x; 1.1910x over previous
#include <cuda_runtime.h>
#include <math.h>

#define BB 4096
#define TT 200
#define DD 64
#define H1 80
#define H2 40
#define NEG_BIG_F (-4294967295.0f)

// One block per batch element b. 256 threads, 2 CTAs/SM.
// Phase 1: fold W1 with q -> per-b Wk[80][64] (shared) + bias c[80].
// Phase 2: thread t computes MLP score; 64-dot uses float4 accumulators and
//          j unrolled by 2 (8 independent FMA chains/thread).
// Phase 3: block softmax. Phase 4: attn @ V.
__global__ __launch_bounds__(256, 2)
void din_attn_kernel(const float* __restrict__ q, const float* __restrict__ k,
                     const float* __restrict__ v, const int* __restrict__ mask,
                     const float* __restrict__ W1, const float* __restrict__ b1,
                     const float* __restrict__ W2, const float* __restrict__ b2,
                     const float* __restrict__ Wf, const float* __restrict__ bf,
                     float* __restrict__ out)
{
    __shared__ __align__(16) float q_sh[DD];
    __shared__ __align__(16) float Wk_sh[H1 * DD];    // [j][i]
    __shared__ __align__(16) float W2_sh[H1 * H2];    // [j][g]
    __shared__ __align__(16) float c_sh[H1];
    __shared__ __align__(16) float b2_sh[H2];
    __shared__ __align__(16) float Wf_sh[H2];
    __shared__ float sc_sh[TT];
    __shared__ float red_sh[8];
    __shared__ float part_sh[256];
    __shared__ float mx_sh, inv_sh;

    const int tid = threadIdx.x;
    const int b   = blockIdx.x;

    if (tid < DD) q_sh[tid] = q[b * DD + tid];
    __syncthreads();

    // ---- Phase 1: fold weights ----
    for (int idx = tid; idx < DD * H1; idx += 256) {
        int i = idx / H1;
        int j = idx % H1;
        float w = W1[(64 + i) * H1 + j]
                - W1[(128 + i) * H1 + j]
                + q_sh[i] * W1[(192 + i) * H1 + j];
        Wk_sh[j * DD + i] = w;
    }
    for (int idx = tid; idx < H1 * H2; idx += 256) W2_sh[idx] = W2[idx];
    if (tid < H2) { b2_sh[tid] = b2[tid]; Wf_sh[tid] = Wf[tid]; }
    if (tid < H1) {
        float acc = b1[tid];
        #pragma unroll 8
        for (int i = 0; i < DD; i++)
            acc += q_sh[i] * (W1[i * H1 + tid] + W1[(128 + i) * H1 + tid]);
        c_sh[tid] = acc;
    }
    __syncthreads();

    // ---- Phase 2: per-token MLP score ----
    if (tid < TT) {
        const float4* kp = (const float4*)(k + ((size_t)b * TT + tid) * DD);
        float4 kk[16];
        #pragma unroll
        for (int ii = 0; ii < 16; ii++) kk[ii] = kp[ii];

        const int m0 = mask[(size_t)b * TT + tid];

        float4 h2a[10];
        #pragma unroll
        for (int g = 0; g < 10; g++) h2a[g] = ((const float4*)b2_sh)[g];

        #pragma unroll 1
        for (int j = 0; j < H1; j += 2) {
            // --- two 64-dots with float4 accumulators: 8 independent chains ---
            const float4* wrA = (const float4*)(Wk_sh + j * DD);
            const float4* wrB = (const float4*)(Wk_sh + (j + 1) * DD);
            float4 aA = make_float4(0.f, 0.f, 0.f, 0.f);
            float4 aB = make_float4(0.f, 0.f, 0.f, 0.f);
            #pragma unroll
            for (int ii = 0; ii < 16; ii++) {
                float4 kkv = kk[ii];
                float4 wA = wrA[ii];
                float4 wB = wrB[ii];
                aA.x = fmaf(kkv.x, wA.x, aA.x);
                aA.y = fmaf(kkv.y, wA.y, aA.y);
                aA.z = fmaf(kkv.z, wA.z, aA.z);
                aA.w = fmaf(kkv.w, wA.w, aA.w);
                aB.x = fmaf(kkv.x, wB.x, aB.x);
                aB.y = fmaf(kkv.y, wB.y, aB.y);
                aB.z = fmaf(kkv.z, wB.z, aB.z);
                aB.w = fmaf(kkv.w, wB.w, aB.w);
            }
            float hA = fmaxf(c_sh[j]     + ((aA.x + aA.y) + (aA.z + aA.w)), 0.0f);
            float hB = fmaxf(c_sh[j + 1] + ((aB.x + aB.y) + (aB.z + aB.w)), 0.0f);

            const float4* w2A = (const float4*)(W2_sh + j * H2);
            const float4* w2B = (const float4*)(W2_sh + (j + 1) * H2);
            #pragma unroll
            for (int g = 0; g < 10; g++) {
                float4 wA = w2A[g];
                float4 wB = w2B[g];
                h2a[g].x = fmaf(hA, wA.x, h2a[g].x);
                h2a[g].y = fmaf(hA, wA.y, h2a[g].y);
                h2a[g].z = fmaf(hA, wA.z, h2a[g].z);
                h2a[g].w = fmaf(hA, wA.w, h2a[g].w);
                h2a[g].x = fmaf(hB, wB.x, h2a[g].x);
                h2a[g].y = fmaf(hB, wB.y, h2a[g].y);
                h2a[g].z = fmaf(hB, wB.z, h2a[g].z);
                h2a[g].w = fmaf(hB, wB.w, h2a[g].w);
            }
        }

        float s = bf[0];
        const float4* wfr = (const float4*)Wf_sh;
        #pragma unroll
        for (int g = 0; g < 10; g++) {
            float4 w = wfr[g];
            s = fmaf(fmaxf(h2a[g].x, 0.0f), w.x, s);
            s = fmaf(fmaxf(h2a[g].y, 0.0f), w.y, s);
            s = fmaf(fmaxf(h2a[g].z, 0.0f), w.z, s);
            s = fmaf(fmaxf(h2a[g].w, 0.0f), w.w, s);
        }
        if (m0 == 0) s = NEG_BIG_F;
        sc_sh[tid] = s;
    }
    __syncthreads();

    // ---- Phase 3: softmax over T ----
    float mval = (tid < TT) ? sc_sh[tid] : -3.0e38f;
    #pragma unroll
    for (int o = 16; o; o >>= 1)
        mval = fmaxf(mval, __shfl_xor_sync(0xffffffffu, mval, o));
    if ((tid & 31) == 0) red_sh[tid >> 5] = mval;
    __syncthreads();
    if (tid == 0) {
        float m = red_sh[0];
        #pragma unroll
        for (int w = 1; w < 8; w++) m = fmaxf(m, red_sh[w]);
        mx_sh = m;
    }
    __syncthreads();
    const float mx = mx_sh;
    float e = (tid < TT) ? __expf(sc_sh[tid] - mx) : 0.0f;
    if (tid < TT) sc_sh[tid] = e;
    float sval = e;
    #pragma unroll
    for (int o = 16; o; o >>= 1)
        sval += __shfl_xor_sync(0xffffffffu, sval, o);
    if ((tid & 31) == 0) red_sh[tid >> 5] = sval;
    __syncthreads();
    if (tid == 0) {
        float sm = 0.0f;
        #pragma unroll
        for (int w = 0; w < 8; w++) sm += red_sh[w];
        inv_sh = 1.0f / sm;
    }
    __syncthreads();

    // ---- Phase 4: out = attn @ V ----
    const float inv = inv_sh;
    const int dd = tid & 63;
    const int p  = tid >> 6;
    const float* vb = v + (size_t)b * TT * DD;
    float a0 = 0.f, a1 = 0.f;
    const int t0 = p * 50;
    #pragma unroll 5
    for (int t = t0; t < t0 + 50; t += 2) {
        a0 = fmaf(sc_sh[t],     vb[(size_t)t * DD + dd],       a0);
        a1 = fmaf(sc_sh[t + 1], vb[(size_t)(t + 1) * DD + dd], a1);
    }
    part_sh[tid] = a0 + a1;
    __syncthreads();
    if (tid < DD) {
        float r = part_sh[tid] + part_sh[tid + 64] + part_sh[tid + 128] + part_sh[tid + 192];
        out[(size_t)b * DD + tid] = r * inv;
    }
}

extern "C" void kernel_launch(void* const* d_in, const int* in_sizes, int n_in,
                              void* d_out, int out_size)
{
    const float* q    = (const float*)d_in[0];
    const float* k    = (const float*)d_in[1];
    const float* v    = (const float*)d_in[2];
    const int*   mask = (const int*)  d_in[3];
    const float* W1   = (const float*)d_in[4];
    const float* b1   = (const float*)d_in[5];
    const float* W2   = (const float*)d_in[6];
    const float* b2   = (const float*)d_in[7];
    const float* Wf   = (const float*)d_in[8];
    const float* bf   = (const float*)d_in[9];
    float* out = (float*)d_out;

    din_attn_kernel<<<BB, 256>>>(q, k, v, mask, W1, b1, W2, b2, Wf, bf, out);
}